// round 15
// baseline (speedup 1.0000x reference)
#include <cuda_runtime.h>
#include <cuda_fp16.h>
#include <math.h>
#include <stdint.h>

#define N_PATCH 676
#define D_DIM   384
#define M_LIB   100000

#define TILE_P  128               /* patches per CTA (MMA M) */
#define TILE_L  64                /* lib rows per chunk (MMA N) */
#define TK      32
#define NKC     (D_DIM/TK)        /* 12 */
#define NCHUNKS 1563              /* ceil(100000/64) */
#define PGROUPS 6
#define SPLITS  24
#define GRID_GEMM (PGROUPS*SPLITS)  /* 144 */

#define IMG   224
#define FMAP  26
#define KS    33
#define KHALF 16

#define WD_BLOCKS 256
#define WD_WARPS  (WD_BLOCKS*8)

/* ---- smem layout (bytes) ---- */
#define A_H     0                 /* patch hi: 12 chunks x 8KB = 96KB */
#define A_L     98304             /* patch lo: 96KB */
#define BH_BASE 196608            /* lib hi, 2 bufs x 4KB */
#define BL_BASE 204800            /* lib lo, 2 bufs x 4KB */
#define SY2_    212992            /* 2 x 64 f32 */
#define SX2_    213504            /* 128 f32 */
#define RED_    214016            /* 256 u64 */
#define SMEM_SZ 216064

#define SWZ64(o) ((o) ^ (((o) >> 3) & 0x30))
#define INFF __int_as_float(0x7f800000)

/* ---------------- device scratch ---------------- */
__device__ unsigned long long g_minpack[N_PATCH];
__device__ float g_minval[N_PATCH];
__device__ int   g_sidx;
__device__ int   g_mstar;
__device__ int   g_nn1;
__device__ int   g_nn2;
__device__ float g_sstar;
__device__ unsigned long long g_top3_scratch[WD_WARPS*3];
__device__ float g_gw[KS];
__device__ float g_up[IMG*IMG];
__device__ float g_tmp[IMG*IMG];

/* ---------------- helpers ---------------- */
__device__ __forceinline__ uint32_t smem_u32(const void* p) {
    uint32_t a;
    asm("{ .reg .u64 t; cvta.to.shared.u64 t, %1; cvt.u32.u64 %0, t; }" : "=r"(a) : "l"(p));
    return a;
}
__device__ __forceinline__ void ldm4(uint32_t* r, uint32_t addr) {
    asm volatile("ldmatrix.sync.aligned.m8n8.x4.shared.b16 {%0,%1,%2,%3}, [%4];"
        : "=r"(r[0]), "=r"(r[1]), "=r"(r[2]), "=r"(r[3]) : "r"(addr));
}
__device__ __forceinline__ void mma16816(float* c, const uint32_t* a, uint32_t b0, uint32_t b1) {
    asm volatile("mma.sync.aligned.m16n8k16.row.col.f32.f16.f16.f32 "
        "{%0,%1,%2,%3}, {%4,%5,%6,%7}, {%8,%9}, {%0,%1,%2,%3};"
        : "+f"(c[0]), "+f"(c[1]), "+f"(c[2]), "+f"(c[3])
        : "r"(a[0]), "r"(a[1]), "r"(a[2]), "r"(a[3]), "r"(b0), "r"(b1));
}
/* split f32 pair -> packed fp16x2 hi + lo(residual) */
__device__ __forceinline__ void hsplit(float a, float b, uint32_t& h, uint32_t& l) {
    __half ha = __float2half_rn(a), hb = __float2half_rn(b);
    float ra = a - __half2float(ha), rb = b - __half2float(hb);
    __half la = __float2half_rn(ra), lb = __float2half_rn(rb);
    h = ((uint32_t)__half_as_ushort(hb) << 16) | (uint32_t)__half_as_ushort(ha);
    l = ((uint32_t)__half_as_ushort(lb) << 16) | (uint32_t)__half_as_ushort(la);
}

/* ---------------- init minpack ---------------- */
__global__ void k_prep() {
    int t = blockIdx.x*blockDim.x + threadIdx.x;
    if (t < N_PATCH) g_minpack[t] = ~0ull;
}

/* ============ main: split-fp16 HMMA cdist, lib streamed once ============ */
__global__ void __launch_bounds__(256) k_gemm(const float* __restrict__ patch,
                                              const float* __restrict__ lib) {
    extern __shared__ char smc[];
    const uint32_t sb = smem_u32(smc);
    float* sy2 = (float*)(smc + SY2_);
    float* sx2 = (float*)(smc + SX2_);
    unsigned long long* red = (unsigned long long*)(smc + RED_);

    const int tid  = threadIdx.x;
    const int lane = tid & 31;
    const int wid  = tid >> 5;
    const int wrow = wid >> 1;          /* patch-warp row 0..3 */
    const int wn   = wid & 1;           /* lib-col warp 0..1 */
    const int g    = blockIdx.x / SPLITS;
    const int s    = blockIdx.x % SPLITS;
    const int pbase = g * TILE_P;
    const int c0 = (s * NCHUNKS) / SPLITS;
    const int c1 = ((s + 1) * NCHUNKS) / SPLITS;
    const int tot = (c1 - c0) * NKC;
    const int fg = lane >> 3, fr = lane & 7;

    /* ---- prologue: patch -> persistent smem hi/lo (per-chunk blocks) + x2 ---- */
    {
        const int row = tid >> 1, h16 = tid & 1;
        const int grow = pbase + row;
        float x2 = 0.f;
        for (int c = 0; c < NKC; c++) {
            float4 v[4];
            if (grow < N_PATCH) {
                const float4* p = (const float4*)(patch + (size_t)grow*D_DIM + c*TK + h16*16);
                v[0]=p[0]; v[1]=p[1]; v[2]=p[2]; v[3]=p[3];
            } else { v[0]=v[1]=v[2]=v[3]=make_float4(0,0,0,0); }
            uint32_t h[8], l[8];
#pragma unroll
            for (int q = 0; q < 4; q++) {
                x2 += v[q].x*v[q].x + v[q].y*v[q].y + v[q].z*v[q].z + v[q].w*v[q].w;
                hsplit(v[q].x, v[q].y, h[q*2+0], l[q*2+0]);
                hsplit(v[q].z, v[q].w, h[q*2+1], l[q*2+1]);
            }
            const uint32_t o0 = SWZ64((uint32_t)row*64u + (uint32_t)(h16*2+0)*16u);
            const uint32_t o1 = SWZ64((uint32_t)row*64u + (uint32_t)(h16*2+1)*16u);
            *(uint4*)(smc + A_H + c*8192 + o0) = make_uint4(h[0],h[1],h[2],h[3]);
            *(uint4*)(smc + A_H + c*8192 + o1) = make_uint4(h[4],h[5],h[6],h[7]);
            *(uint4*)(smc + A_L + c*8192 + o0) = make_uint4(l[0],l[1],l[2],l[3]);
            *(uint4*)(smc + A_L + c*8192 + o1) = make_uint4(l[4],l[5],l[6],l[7]);
        }
        x2 += __shfl_xor_sync(0xffffffffu, x2, 1);
        if (h16 == 0) sx2[row] = x2;
    }
    __syncthreads();

    /* owned patch rows + their x2 (constant per thread) */
    float x2r[2][2];
    int   mlr[2][2];
#pragma unroll
    for (int mt = 0; mt < 2; mt++)
#pragma unroll
        for (int mr = 0; mr < 2; mr++) {
            const int ml = wrow*32 + mt*16 + (lane >> 2) + (mr << 3);
            mlr[mt][mr] = ml;
            x2r[mt][mr] = sx2[ml];
        }

    float acc[2][4][4];
#pragma unroll
    for (int a = 0; a < 2; a++)
#pragma unroll
        for (int b = 0; b < 4; b++)
#pragma unroll
            for (int c = 0; c < 4; c++) acc[a][b][c] = 0.f;

    unsigned long long best[2][2] = {{~0ull, ~0ull}, {~0ull, ~0ull}};
    float y2acc = 0.f;
    float4 v0, v1;
    const float4 Z4 = make_float4(0.f,0.f,0.f,0.f);

#define PREF(tt, dv0, dv1) do { \
    const int _t = (tt); const int _j = _t / NKC; const int _k = _t - _j*NKC; \
    const int _row = (c0 + _j)*TILE_L + (tid >> 2); \
    if (_t < tot && _row < M_LIB) { \
        const float4* _p = (const float4*)(lib + (size_t)_row*D_DIM + _k*TK + (tid&3)*8); \
        dv0 = _p[0]; dv1 = _p[1]; \
    } else { dv0 = Z4; dv1 = Z4; } \
    float _ss = dv0.x*dv0.x+dv0.y*dv0.y+dv0.z*dv0.z+dv0.w*dv0.w \
              + dv1.x*dv1.x+dv1.y*dv1.y+dv1.z*dv1.z+dv1.w*dv1.w; \
    _ss += __shfl_xor_sync(0xffffffffu, _ss, 1); \
    _ss += __shfl_xor_sync(0xffffffffu, _ss, 2); \
    y2acc += _ss; \
} while (0)

#define STSB(bufb) do { \
    uint32_t h0,h1,h2,h3,l0,l1,l2,l3; \
    hsplit(v0.x,v0.y,h0,l0); hsplit(v0.z,v0.w,h1,l1); \
    hsplit(v1.x,v1.y,h2,l2); hsplit(v1.z,v1.w,h3,l3); \
    const uint32_t _o = SWZ64((uint32_t)(tid>>2)*64u + (uint32_t)(tid&3)*16u); \
    *(uint4*)(smc + BH_BASE + (bufb)*4096 + _o) = make_uint4(h0,h1,h2,h3); \
    *(uint4*)(smc + BL_BASE + (bufb)*4096 + _o) = make_uint4(l0,l1,l2,l3); \
} while (0)

    /* preamble: stage step 0 */
    PREF(0, v0, v1);
    STSB(0u);
    __syncthreads();

    for (int t = 0; t < tot; t++) {
        const int j = t / NKC;
        const int k = t - j*NKC;
        const uint32_t buf = (uint32_t)(t & 1);

        float4 nv0, nv1;
        PREF(t + 1, nv0, nv1);

        if (k == 10) {
            /* y2 for chunk j is now complete */
            if ((tid & 3) == 0) {
                const int row = (c0 + j)*TILE_L + (tid >> 2);
                sy2[(j & 1)*64 + (tid >> 2)] = (row < M_LIB) ? y2acc : INFF;
            }
            y2acc = 0.f;
        }

        const uint32_t bhb = sb + BH_BASE + buf*4096u;
        const uint32_t blb = sb + BL_BASE + buf*4096u;
        const uint32_t ahb = sb + A_H + (uint32_t)(k*8192);
        const uint32_t alb = sb + A_L + (uint32_t)(k*8192);
#pragma unroll
        for (int sh = 0; sh < 2; sh++) {
            uint32_t ah[2][4], al[2][4], bh[2][4], bl[2][4];
#pragma unroll
            for (int mt = 0; mt < 2; mt++) {
                const uint32_t row = (uint32_t)(wrow*32 + mt*16 + fr + ((fg & 1) << 3));
                const uint32_t o = SWZ64(row*64u + (uint32_t)sh*32u + (uint32_t)((fg >> 1) << 4));
                ldm4(ah[mt], ahb + o);
                ldm4(al[mt], alb + o);
            }
#pragma unroll
            for (int bt = 0; bt < 2; bt++) {
                const uint32_t row = (uint32_t)(wn*32 + bt*16 + fr + ((fg >> 1) << 3));
                const uint32_t o = SWZ64(row*64u + (uint32_t)sh*32u + (uint32_t)((fg & 1) << 4));
                ldm4(bh[bt], bhb + o);
                ldm4(bl[bt], blb + o);
            }
#pragma unroll
            for (int mt = 0; mt < 2; mt++)
#pragma unroll
                for (int nt = 0; nt < 4; nt++) {
                    const int bt = nt >> 1, q = (nt & 1) * 2;
                    mma16816(acc[mt][nt], ah[mt], bh[bt][q], bh[bt][q+1]);
                    mma16816(acc[mt][nt], ah[mt], bl[bt][q], bl[bt][q+1]);
                    mma16816(acc[mt][nt], al[mt], bh[bt][q], bh[bt][q+1]);
                }
        }

        if (t + 1 < tot) { v0 = nv0; v1 = nv1; STSB(buf ^ 1u); }
        __syncthreads();

        if (k == NKC - 1) {
            /* epilogue for lib chunk j: fold into running per-row min */
            const float* sy = sy2 + (j & 1)*64;
            const int lb = (c0 + j)*TILE_L;
#pragma unroll
            for (int nt = 0; nt < 4; nt++)
#pragma unroll
                for (int p = 0; p < 2; p++) {
                    const int nl = wn*32 + nt*8 + ((lane & 3) << 1) + p;
                    const float y2v = sy[nl];
#pragma unroll
                    for (int mt = 0; mt < 2; mt++)
#pragma unroll
                        for (int mr = 0; mr < 2; mr++) {
                            const float d2 = fmaxf(x2r[mt][mr] + y2v
                                                   - 2.f*acc[mt][nt][mr*2 + p], 0.f);
                            const unsigned long long pk =
                                ((unsigned long long)__float_as_uint(d2) << 32) |
                                (unsigned)(lb + nl);
                            if (pk < best[mt][mr]) best[mt][mr] = pk;
                        }
                }
#pragma unroll
            for (int a = 0; a < 2; a++)
#pragma unroll
                for (int b = 0; b < 4; b++)
#pragma unroll
                    for (int c = 0; c < 4; c++) acc[a][b][c] = 0.f;
        }
    }
#undef PREF
#undef STSB

    /* final reduce: 4 lanes sharing a row, then 2 wn warps, then atomic */
#pragma unroll
    for (int mt = 0; mt < 2; mt++)
#pragma unroll
        for (int mr = 0; mr < 2; mr++) {
            unsigned long long b = best[mt][mr];
            unsigned long long o1 = __shfl_xor_sync(0xffffffffu, b, 1); if (o1 < b) b = o1;
            unsigned long long o2 = __shfl_xor_sync(0xffffffffu, b, 2); if (o2 < b) b = o2;
            if ((lane & 3) == 0) red[mlr[mt][mr]*2 + wn] = b;
        }
    __syncthreads();
    if (tid < TILE_P) {
        unsigned long long b = red[tid*2];
        if (red[tid*2 + 1] < b) b = red[tid*2 + 1];
        const int row = pbase + tid;
        if (row < N_PATCH) atomicMin(&g_minpack[row], b);
    }
}

/* ---------------- argmax over min_val (tie -> lowest idx) ---------------- */
__global__ void k_argmax() {
    __shared__ float sv[1024];
    __shared__ int   si[1024];
    int t = threadIdx.x;
    float v = -1.f;
    if (t < N_PATCH) {
        unsigned long long p = g_minpack[t];
        v = sqrtf(__uint_as_float((unsigned)(p >> 32)));
        g_minval[t] = v;
    }
    sv[t] = v; si[t] = t;
    __syncthreads();
    for (int s = 512; s > 0; s >>= 1) {
        if (t < s) {
            if (sv[t+s] > sv[t] || (sv[t+s] == sv[t] && si[t+s] < si[t])) {
                sv[t] = sv[t+s]; si[t] = si[t+s];
            }
        }
        __syncthreads();
    }
    if (t == 0) {
        int sidx = si[0];
        g_sidx  = sidx;
        g_sstar = sv[0];
        g_mstar = (int)(unsigned)(g_minpack[sidx] & 0xffffffffull);
    }
}

__device__ __forceinline__ void ins3(unsigned long long& t0, unsigned long long& t1,
                                     unsigned long long& t2, unsigned long long p) {
    if (p < t2) {
        t2 = p;
        if (t2 < t1) { unsigned long long x = t1; t1 = t2; t2 = x; }
        if (t1 < t0) { unsigned long long x = t0; t0 = t1; t1 = x; }
    }
}

__global__ void k_wdist(const float* __restrict__ lib) {
    int gw = blockIdx.x*8 + (threadIdx.x >> 5);
    int lane = threadIdx.x & 31;
    const float4* ms = (const float4*)(lib + (size_t)g_mstar * D_DIM);
    unsigned long long t0 = ~0ull, t1 = ~0ull, t2 = ~0ull;
    for (int m = gw; m < M_LIB; m += WD_WARPS) {
        const float4* y = (const float4*)(lib + (size_t)m * D_DIM);
        float s = 0.f;
#pragma unroll
        for (int j = 0; j < 3; j++) {
            float4 a = ms[lane + 32*j];
            float4 b = y[lane + 32*j];
            float dx = a.x-b.x, dy = a.y-b.y, dz = a.z-b.z, dw = a.w-b.w;
            s += dx*dx + dy*dy + dz*dz + dw*dw;
        }
        for (int o = 16; o; o >>= 1) s += __shfl_xor_sync(0xffffffffu, s, o);
        unsigned long long p =
            ((unsigned long long)__float_as_uint(sqrtf(s)) << 32) | (unsigned)m;
        ins3(t0, t1, t2, p);
    }
    if (lane == 0) {
        g_top3_scratch[gw*3+0] = t0;
        g_top3_scratch[gw*3+1] = t1;
        g_top3_scratch[gw*3+2] = t2;
    }
}

__global__ void k_merge() {
    __shared__ unsigned long long sm[256*3];
    int t = threadIdx.x;
    unsigned long long t0 = ~0ull, t1 = ~0ull, t2 = ~0ull;
    for (int i = t; i < WD_WARPS*3; i += 256) ins3(t0, t1, t2, g_top3_scratch[i]);
    sm[t*3+0] = t0; sm[t*3+1] = t1; sm[t*3+2] = t2;
    __syncthreads();
    if (t < 32) {
        for (int k = 1; k < 8; k++) {
            int o = (t + 32*k)*3;
            ins3(t0, t1, t2, sm[o]); ins3(t0, t1, t2, sm[o+1]); ins3(t0, t1, t2, sm[o+2]);
        }
        sm[t*3+0] = t0; sm[t*3+1] = t1; sm[t*3+2] = t2;
    }
    __syncthreads();
    if (t == 0) {
        for (int k = 1; k < 32; k++) {
            int o = k*3;
            ins3(t0, t1, t2, sm[o]); ins3(t0, t1, t2, sm[o+1]); ins3(t0, t1, t2, sm[o+2]);
        }
        g_nn1 = (int)(unsigned)(t1 & 0xffffffffull);
        g_nn2 = (int)(unsigned)(t2 & 0xffffffffull);
    }
}

__global__ void k_score(const float* __restrict__ patch, const float* __restrict__ lib,
                        float* __restrict__ out, int write_s) {
    __shared__ float kd[2];
    int w = threadIdx.x >> 5, lane = threadIdx.x & 31;
    int nn = (w == 0) ? g_nn1 : g_nn2;
    const float4* a = (const float4*)(patch + (size_t)g_sidx * D_DIM);
    const float4* b = (const float4*)(lib + (size_t)nn * D_DIM);
    float s = 0.f;
#pragma unroll
    for (int j = 0; j < 3; j++) {
        float4 x = a[lane + 32*j];
        float4 y = b[lane + 32*j];
        float dx = x.x-y.x, dy = x.y-y.y, dz = x.z-y.z, dw = x.w-y.w;
        s += dx*dx + dy*dy + dz*dz + dw*dw;
    }
    for (int o = 16; o; o >>= 1) s += __shfl_xor_sync(0xffffffffu, s, o);
    if (lane == 0) kd[w] = sqrtf(s);
    __syncthreads();
    if (threadIdx.x == 0 && write_s) {
        float Ds = sqrtf((float)D_DIM);
        float sstar = g_sstar;
        float wgt = 1.f - expf(sstar/Ds) / (expf(kd[0]/Ds) + expf(kd[1]/Ds));
        out[0] = wgt * sstar;
    }
}

__global__ void k_weights() {
    double ww[KS]; double sum = 0.0;
    for (int i = 0; i < KS; i++) {
        double x = (double)i - (double)(KS-1)/2.0;
        ww[i] = exp(-0.5 * (x/4.0) * (x/4.0));
        sum += ww[i];
    }
    for (int i = 0; i < KS; i++) g_gw[i] = (float)(ww[i] / sum);
}

__global__ void k_resize() {
    int o = blockIdx.x*blockDim.x + threadIdx.x;
    if (o >= IMG*IMG) return;
    int oy = o / IMG, ox = o % IMG;
    const float sc = (float)FMAP / (float)IMG;
    float sy = (oy + 0.5f)*sc - 0.5f;
    float sx = (ox + 0.5f)*sc - 0.5f;
    int y0 = (int)floorf(sy); float fy = sy - (float)y0;
    int x0 = (int)floorf(sx); float fx = sx - (float)x0;
    int y0c = min(max(y0, 0), FMAP-1), y1c = min(max(y0+1, 0), FMAP-1);
    int x0c = min(max(x0, 0), FMAP-1), x1c = min(max(x0+1, 0), FMAP-1);
    float v00 = g_minval[y0c*FMAP + x0c], v01 = g_minval[y0c*FMAP + x1c];
    float v10 = g_minval[y1c*FMAP + x0c], v11 = g_minval[y1c*FMAP + x1c];
    g_up[o] = (1.f-fy)*((1.f-fx)*v00 + fx*v01) + fy*((1.f-fx)*v10 + fx*v11);
}

__device__ __forceinline__ int refl(int q) {
    if (q < 0) q = -q;
    if (q > IMG-1) q = 2*(IMG-1) - q;
    return q;
}

__global__ void k_blurY() {
    int o = blockIdx.x*blockDim.x + threadIdx.x;
    if (o >= IMG*IMG) return;
    int oy = o / IMG, ox = o % IMG;
    float s = 0.f;
#pragma unroll
    for (int t = 0; t < KS; t++)
        s += g_gw[t] * g_up[refl(oy + t - KHALF)*IMG + ox];
    g_tmp[o] = s;
}

__global__ void k_blurX(float* __restrict__ map_out) {
    int o = blockIdx.x*blockDim.x + threadIdx.x;
    if (o >= IMG*IMG) return;
    int oy = o / IMG, ox = o % IMG;
    float s = 0.f;
#pragma unroll
    for (int t = 0; t < KS; t++)
        s += g_gw[t] * g_tmp[oy*IMG + refl(ox + t - KHALF)];
    map_out[o] = s;
}

/* ---------------- launch ---------------- */
extern "C" void kernel_launch(void* const* d_in, const int* in_sizes, int n_in,
                              void* d_out, int out_size) {
    const float* patch = (const float*)d_in[0];
    const float* lib   = (const float*)d_in[1];
    float* out = (float*)d_out;
    int has_scalar = (out_size > IMG*IMG) ? 1 : 0;
    float* map_out = out + has_scalar;

    cudaFuncSetAttribute(k_gemm, cudaFuncAttributeMaxDynamicSharedMemorySize, SMEM_SZ);

    k_prep<<<3, 256>>>();
    k_gemm<<<GRID_GEMM, 256, SMEM_SZ>>>(patch, lib);
    k_argmax<<<1, 1024>>>();
    k_wdist<<<WD_BLOCKS, 256>>>(lib);
    k_merge<<<1, 256>>>();
    k_score<<<1, 64>>>(patch, lib, out, has_scalar);
    k_weights<<<1, 1>>>();
    k_resize<<<196, 256>>>();
    k_blurY<<<196, 256>>>();
    k_blurX<<<196, 256>>>(map_out);
}

// round 16
// speedup vs baseline: 1.4350x; 1.4350x over previous
#include <cuda_runtime.h>
#include <cuda_fp16.h>
#include <math.h>
#include <stdint.h>

#define N_PATCH 676
#define N_PAD   704
#define D_DIM   384
#define M_LIB   100000
#define TILE_M  128
#define TILE_N  64
#define TK      32
#define NCHUNK  (D_DIM/TK)            /* 12 */
#define NBLK_M  ((M_LIB + TILE_M - 1)/TILE_M)   /* 782 */

#define IMG   224
#define FMAP  26
#define KS    33
#define KHALF 16

#define WD_BLOCKS 256
#define WD_WARPS  (WD_BLOCKS*8)

/* smem layout (bytes), double buffer of (AH,AL,BH,BL) */
#define BUFSZ  24576
#define AH_    0
#define AL_    8192
#define BH_    16384
#define BL_    20480
#define RED_   49152      /* u64[256] */
#define SX2_   51200      /* f32[64]  */
#define SY2_   51456      /* f32[128] */
#define SMEM_SZ 52224

#define SWZ64(o) ((o) ^ (((o) >> 3) & 0x30))
#define INFF __int_as_float(0x7f800000)

/* ---------------- device scratch ---------------- */
__device__ __half g_lib_h[(size_t)M_LIB * D_DIM];   /* 76.8 MB */
__device__ __half g_lib_l[(size_t)M_LIB * D_DIM];   /* 76.8 MB */
__device__ __half g_pat_h[N_PAD * D_DIM];
__device__ __half g_pat_l[N_PAD * D_DIM];
__device__ float g_x2[N_PAD];
__device__ float g_y2[M_LIB];
__device__ unsigned long long g_minpack[N_PATCH];
__device__ float g_minval[N_PATCH];
__device__ int   g_sidx;
__device__ int   g_mstar;
__device__ int   g_nn1;
__device__ int   g_nn2;
__device__ float g_sstar;
__device__ unsigned long long g_top3_scratch[WD_WARPS*3];
__device__ float g_gw[KS];
__device__ float g_up[IMG*IMG];
__device__ float g_tmp[IMG*IMG];

/* ---------------- helpers ---------------- */
__device__ __forceinline__ uint32_t smem_u32(const void* p) {
    uint32_t a;
    asm("{ .reg .u64 t; cvta.to.shared.u64 t, %1; cvt.u32.u64 %0, t; }" : "=r"(a) : "l"(p));
    return a;
}
__device__ __forceinline__ void ldm4(uint32_t* r, uint32_t addr) {
    asm volatile("ldmatrix.sync.aligned.m8n8.x4.shared.b16 {%0,%1,%2,%3}, [%4];"
        : "=r"(r[0]), "=r"(r[1]), "=r"(r[2]), "=r"(r[3]) : "r"(addr));
}
__device__ __forceinline__ void mma16816(float* c, const uint32_t* a, uint32_t b0, uint32_t b1) {
    asm volatile("mma.sync.aligned.m16n8k16.row.col.f32.f16.f16.f32 "
        "{%0,%1,%2,%3}, {%4,%5,%6,%7}, {%8,%9}, {%0,%1,%2,%3};"
        : "+f"(c[0]), "+f"(c[1]), "+f"(c[2]), "+f"(c[3])
        : "r"(a[0]), "r"(a[1]), "r"(a[2]), "r"(a[3]), "r"(b0), "r"(b1));
}
/* split f32 pair -> packed fp16x2 hi + lo(residual) */
__device__ __forceinline__ void hsplit(float a, float b, uint32_t& h, uint32_t& l) {
    __half ha = __float2half_rn(a), hb = __float2half_rn(b);
    float ra = a - __half2float(ha), rb = b - __half2float(hb);
    __half la = __float2half_rn(ra), lb = __float2half_rn(rb);
    h = ((uint32_t)__half_as_ushort(hb) << 16) | (uint32_t)__half_as_ushort(ha);
    l = ((uint32_t)__half_as_ushort(lb) << 16) | (uint32_t)__half_as_ushort(la);
}

/* ------- prep: convert patch -> fp16 hi/lo, x2, init minpack (704 warps) ------- */
__global__ void k_prep(const float* __restrict__ patch) {
    int gt = blockIdx.x*blockDim.x + threadIdx.x;
    if (gt < N_PATCH) g_minpack[gt] = ~0ull;
    int w = gt >> 5, lane = gt & 31;
    if (w >= N_PAD) return;
    float s = 0.f;
#pragma unroll
    for (int j = 0; j < 3; j++) {
        float4 v = make_float4(0.f,0.f,0.f,0.f);
        if (w < N_PATCH)
            v = ((const float4*)(patch + (size_t)w * D_DIM))[lane + 32*j];
        s += v.x*v.x + v.y*v.y + v.z*v.z + v.w*v.w;
        uint32_t h0,h1,l0,l1;
        hsplit(v.x, v.y, h0, l0); hsplit(v.z, v.w, h1, l1);
        size_t idx = (size_t)w * D_DIM + 4*(lane + 32*j);
        *(uint2*)(g_pat_h + idx) = make_uint2(h0, h1);
        *(uint2*)(g_pat_l + idx) = make_uint2(l0, l1);
    }
    for (int o = 16; o; o >>= 1) s += __shfl_xor_sync(0xffffffffu, s, o);
    if (lane == 0) g_x2[w] = s;
}

/* ------- convert lib -> fp16 hi/lo + y2 (100000 warps) ------- */
__global__ void k_conv_lib(const float* __restrict__ lib) {
    int gw = blockIdx.x*8 + (threadIdx.x >> 5);
    int lane = threadIdx.x & 31;
    if (gw >= M_LIB) return;
    const float4* src = (const float4*)(lib + (size_t)gw * D_DIM);
    float s = 0.f;
#pragma unroll
    for (int j = 0; j < 3; j++) {
        float4 v = src[lane + 32*j];
        s += v.x*v.x + v.y*v.y + v.z*v.z + v.w*v.w;
        uint32_t h0,h1,l0,l1;
        hsplit(v.x, v.y, h0, l0); hsplit(v.z, v.w, h1, l1);
        size_t idx = (size_t)gw * D_DIM + 4*(lane + 32*j);
        *(uint2*)(g_lib_h + idx) = make_uint2(h0, h1);
        *(uint2*)(g_lib_l + idx) = make_uint2(l0, l1);
    }
    for (int o = 16; o; o >>= 1) s += __shfl_xor_sync(0xffffffffu, s, o);
    if (lane == 0) g_y2[gw] = s;
}

/* ============ main: split-fp16 HMMA cdist + fused min/argmin ============ */
__global__ void __launch_bounds__(256, 2) k_gemm() {
    extern __shared__ char smc[];
    const uint32_t sb = smem_u32(smc);
    unsigned long long* red = (unsigned long long*)(smc + RED_);
    float* sx2 = (float*)(smc + SX2_);
    float* sy2 = (float*)(smc + SY2_);

    const int tid  = threadIdx.x;
    const int lane = tid & 31;
    const int wid  = tid >> 5;
    const int wrow = wid >> 1;          /* m-warp row 0..3 (32 m each) */
    const int wn   = wid & 1;           /* n-warp col 0..1 (32 n each) */
    const int mbase = blockIdx.x * TILE_M;

    /* y2 (+inf for padded lib rows) */
    if (tid < TILE_M) {
        int m = mbase + tid;
        sy2[tid] = (m < M_LIB) ? g_y2[m] : INFF;
    }

    /* A mapping: row=tid>>1, k-half=(tid&1)*16 halves */
    const int arow = tid >> 1, ah16 = tid & 1;
    const bool aval = (mbase + arow) < M_LIB;
    const size_t abase = (size_t)(mbase + arow) * D_DIM + ah16*16;
    const uint32_t ao0 = SWZ64((uint32_t)arow*64u + (uint32_t)(ah16*2+0)*16u);
    const uint32_t ao1 = SWZ64((uint32_t)arow*64u + (uint32_t)(ah16*2+1)*16u);

    /* B mapping: row=tid>>2, k-q8=(tid&3)*8 halves */
    const int brrel = tid >> 2, bq8 = tid & 3;
    const uint32_t bo = SWZ64((uint32_t)brrel*64u + (uint32_t)bq8*16u);

    const int fg = lane >> 3, fr = lane & 7;

    uint4 vah0, vah1, val0, val1, vbh, vbl;
    const uint4 Z4 = make_uint4(0,0,0,0);

#define LOADA(kb) do { \
    if (aval) { \
        const uint4* _ph = (const uint4*)(g_lib_h + abase + (kb)); \
        const uint4* _pl = (const uint4*)(g_lib_l + abase + (kb)); \
        vah0 = _ph[0]; vah1 = _ph[1]; val0 = _pl[0]; val1 = _pl[1]; \
    } else { vah0 = Z4; vah1 = Z4; val0 = Z4; val1 = Z4; } } while(0)

#define LOADB(bbase, kb) do { \
    vbh = *(const uint4*)(g_pat_h + (bbase) + (kb)); \
    vbl = *(const uint4*)(g_pat_l + (bbase) + (kb)); } while(0)

#define STSA(dst) do { \
    *(uint4*)(smc + (dst) + AH_ + ao0) = vah0; \
    *(uint4*)(smc + (dst) + AH_ + ao1) = vah1; \
    *(uint4*)(smc + (dst) + AL_ + ao0) = val0; \
    *(uint4*)(smc + (dst) + AL_ + ao1) = val1; } while(0)

#define STSB(dst) do { \
    *(uint4*)(smc + (dst) + BH_ + bo) = vbh; \
    *(uint4*)(smc + (dst) + BL_ + bo) = vbl; } while(0)

    for (int n0 = 0; n0 < N_PAD; n0 += TILE_N) {
        if (tid < TILE_N) sx2[tid] = g_x2[n0 + tid];
        const size_t bbase = (size_t)(n0 + brrel) * D_DIM + bq8*8;

        float acc[2][4][4];
#pragma unroll
        for (int a = 0; a < 2; a++)
#pragma unroll
            for (int b = 0; b < 4; b++)
#pragma unroll
                for (int c = 0; c < 4; c++) acc[a][b][c] = 0.f;

        /* chunk 0 */
        LOADA(0); LOADB(bbase, 0);
        STSA(0); STSB(0);
        __syncthreads();

        for (int c = 0; c < NCHUNK; c++) {
            const bool pf = (c + 1 < NCHUNK);
            if (pf) {
                const int kb = (c+1)*TK;
                LOADA(kb); LOADB(bbase, kb);
            }
            const uint32_t base = (uint32_t)((c & 1) * BUFSZ);
#pragma unroll
            for (int s = 0; s < 2; s++) {
                uint32_t ah[2][4], al[2][4], bhf[2][4], blf[2][4];
#pragma unroll
                for (int mt = 0; mt < 2; mt++) {
                    uint32_t row = (uint32_t)(wrow*32 + mt*16 + fr + ((fg & 1) << 3));
                    uint32_t o = SWZ64(row*64u + (uint32_t)s*32u + (uint32_t)((fg >> 1) << 4));
                    ldm4(ah[mt], sb + base + AH_ + o);
                    ldm4(al[mt], sb + base + AL_ + o);
                }
#pragma unroll
                for (int bt = 0; bt < 2; bt++) {
                    uint32_t row = (uint32_t)(wn*32 + bt*16 + fr + ((fg >> 1) << 3));
                    uint32_t o = SWZ64(row*64u + (uint32_t)s*32u + (uint32_t)((fg & 1) << 4));
                    ldm4(bhf[bt], sb + base + BH_ + o);
                    ldm4(blf[bt], sb + base + BL_ + o);
                }
#pragma unroll
                for (int mt = 0; mt < 2; mt++)
#pragma unroll
                    for (int nt = 0; nt < 4; nt++) {
                        const int bt = nt >> 1, q = (nt & 1) * 2;
                        mma16816(acc[mt][nt], ah[mt], bhf[bt][q], bhf[bt][q+1]);
                        mma16816(acc[mt][nt], ah[mt], blf[bt][q], blf[bt][q+1]);
                        mma16816(acc[mt][nt], al[mt], bhf[bt][q], bhf[bt][q+1]);
                    }
            }
            if (pf) {
                const uint32_t nb = (uint32_t)(((c+1) & 1) * BUFSZ);
                STSA(nb); STSB(nb);
            }
            __syncthreads();
        }

        /* epilogue: d2 + packed argmin, warp-reduce over m-lanes */
#pragma unroll
        for (int nt = 0; nt < 4; nt++)
#pragma unroll
            for (int p = 0; p < 2; p++) {
                const int nl = wn*32 + nt*8 + ((lane & 3) << 1) + p;
                const float x2v = sx2[nl];
                unsigned long long best = ~0ull;
#pragma unroll
                for (int mt = 0; mt < 2; mt++)
#pragma unroll
                    for (int mr = 0; mr < 2; mr++) {
                        const int ml = wrow*32 + mt*16 + (lane >> 2) + (mr << 3);
                        float d2 = fmaxf(x2v + sy2[ml] - 2.f*acc[mt][nt][mr*2 + p], 0.f);
                        unsigned long long pk =
                            ((unsigned long long)__float_as_uint(d2) << 32) |
                            (unsigned)(mbase + ml);
                        if (pk < best) best = pk;
                    }
                unsigned long long o4  = __shfl_xor_sync(0xffffffffu, best, 4);  if (o4  < best) best = o4;
                unsigned long long o8  = __shfl_xor_sync(0xffffffffu, best, 8);  if (o8  < best) best = o8;
                unsigned long long o16 = __shfl_xor_sync(0xffffffffu, best, 16); if (o16 < best) best = o16;
                if ((lane >> 2) == 0) red[wrow*64 + nl] = best;
            }
        __syncthreads();
        if (tid < TILE_N) {
            unsigned long long b = red[tid];
#pragma unroll
            for (int w = 1; w < 4; w++) {
                unsigned long long v = red[w*64 + tid];
                if (v < b) b = v;
            }
            int n = n0 + tid;
            if (n < N_PATCH) atomicMin(&g_minpack[n], b);
        }
        __syncthreads();
    }
#undef LOADA
#undef LOADB
#undef STSA
#undef STSB
}

/* ---------------- argmax over min_val (tie -> lowest idx) ---------------- */
__global__ void k_argmax() {
    __shared__ float sv[1024];
    __shared__ int   si[1024];
    int t = threadIdx.x;
    float v = -1.f;
    if (t < N_PATCH) {
        unsigned long long p = g_minpack[t];
        v = sqrtf(__uint_as_float((unsigned)(p >> 32)));
        g_minval[t] = v;
    }
    sv[t] = v; si[t] = t;
    __syncthreads();
    for (int s = 512; s > 0; s >>= 1) {
        if (t < s) {
            if (sv[t+s] > sv[t] || (sv[t+s] == sv[t] && si[t+s] < si[t])) {
                sv[t] = sv[t+s]; si[t] = si[t+s];
            }
        }
        __syncthreads();
    }
    if (t == 0) {
        int sidx = si[0];
        g_sidx  = sidx;
        g_sstar = sv[0];
        g_mstar = (int)(unsigned)(g_minpack[sidx] & 0xffffffffull);
    }
}

__device__ __forceinline__ void ins3(unsigned long long& t0, unsigned long long& t1,
                                     unsigned long long& t2, unsigned long long p) {
    if (p < t2) {
        t2 = p;
        if (t2 < t1) { unsigned long long x = t1; t1 = t2; t2 = x; }
        if (t1 < t0) { unsigned long long x = t0; t0 = t1; t1 = x; }
    }
}

__global__ void k_wdist(const float* __restrict__ lib) {
    int gw = blockIdx.x*8 + (threadIdx.x >> 5);
    int lane = threadIdx.x & 31;
    const float4* ms = (const float4*)(lib + (size_t)g_mstar * D_DIM);
    unsigned long long t0 = ~0ull, t1 = ~0ull, t2 = ~0ull;
    for (int m = gw; m < M_LIB; m += WD_WARPS) {
        const float4* y = (const float4*)(lib + (size_t)m * D_DIM);
        float s = 0.f;
#pragma unroll
        for (int j = 0; j < 3; j++) {
            float4 a = ms[lane + 32*j];
            float4 b = y[lane + 32*j];
            float dx = a.x-b.x, dy = a.y-b.y, dz = a.z-b.z, dw = a.w-b.w;
            s += dx*dx + dy*dy + dz*dz + dw*dw;
        }
        for (int o = 16; o; o >>= 1) s += __shfl_xor_sync(0xffffffffu, s, o);
        unsigned long long p =
            ((unsigned long long)__float_as_uint(sqrtf(s)) << 32) | (unsigned)m;
        ins3(t0, t1, t2, p);
    }
    if (lane == 0) {
        g_top3_scratch[gw*3+0] = t0;
        g_top3_scratch[gw*3+1] = t1;
        g_top3_scratch[gw*3+2] = t2;
    }
}

__global__ void k_merge() {
    __shared__ unsigned long long sm[256*3];
    int t = threadIdx.x;
    unsigned long long t0 = ~0ull, t1 = ~0ull, t2 = ~0ull;
    for (int i = t; i < WD_WARPS*3; i += 256) ins3(t0, t1, t2, g_top3_scratch[i]);
    sm[t*3+0] = t0; sm[t*3+1] = t1; sm[t*3+2] = t2;
    __syncthreads();
    if (t < 32) {
        for (int k = 1; k < 8; k++) {
            int o = (t + 32*k)*3;
            ins3(t0, t1, t2, sm[o]); ins3(t0, t1, t2, sm[o+1]); ins3(t0, t1, t2, sm[o+2]);
        }
        sm[t*3+0] = t0; sm[t*3+1] = t1; sm[t*3+2] = t2;
    }
    __syncthreads();
    if (t == 0) {
        for (int k = 1; k < 32; k++) {
            int o = k*3;
            ins3(t0, t1, t2, sm[o]); ins3(t0, t1, t2, sm[o+1]); ins3(t0, t1, t2, sm[o+2]);
        }
        g_nn1 = (int)(unsigned)(t1 & 0xffffffffull);
        g_nn2 = (int)(unsigned)(t2 & 0xffffffffull);
    }
}

__global__ void k_score(const float* __restrict__ patch, const float* __restrict__ lib,
                        float* __restrict__ out, int write_s) {
    __shared__ float kd[2];
    int w = threadIdx.x >> 5, lane = threadIdx.x & 31;
    int nn = (w == 0) ? g_nn1 : g_nn2;
    const float4* a = (const float4*)(patch + (size_t)g_sidx * D_DIM);
    const float4* b = (const float4*)(lib + (size_t)nn * D_DIM);
    float s = 0.f;
#pragma unroll
    for (int j = 0; j < 3; j++) {
        float4 x = a[lane + 32*j];
        float4 y = b[lane + 32*j];
        float dx = x.x-y.x, dy = x.y-y.y, dz = x.z-y.z, dw = x.w-y.w;
        s += dx*dx + dy*dy + dz*dz + dw*dw;
    }
    for (int o = 16; o; o >>= 1) s += __shfl_xor_sync(0xffffffffu, s, o);
    if (lane == 0) kd[w] = sqrtf(s);
    __syncthreads();
    if (threadIdx.x == 0 && write_s) {
        float Ds = sqrtf((float)D_DIM);
        float sstar = g_sstar;
        float wgt = 1.f - expf(sstar/Ds) / (expf(kd[0]/Ds) + expf(kd[1]/Ds));
        out[0] = wgt * sstar;
    }
}

__global__ void k_weights() {
    double ww[KS]; double sum = 0.0;
    for (int i = 0; i < KS; i++) {
        double x = (double)i - (double)(KS-1)/2.0;
        ww[i] = exp(-0.5 * (x/4.0) * (x/4.0));
        sum += ww[i];
    }
    for (int i = 0; i < KS; i++) g_gw[i] = (float)(ww[i] / sum);
}

__global__ void k_resize() {
    int o = blockIdx.x*blockDim.x + threadIdx.x;
    if (o >= IMG*IMG) return;
    int oy = o / IMG, ox = o % IMG;
    const float sc = (float)FMAP / (float)IMG;
    float sy = (oy + 0.5f)*sc - 0.5f;
    float sx = (ox + 0.5f)*sc - 0.5f;
    int y0 = (int)floorf(sy); float fy = sy - (float)y0;
    int x0 = (int)floorf(sx); float fx = sx - (float)x0;
    int y0c = min(max(y0, 0), FMAP-1), y1c = min(max(y0+1, 0), FMAP-1);
    int x0c = min(max(x0, 0), FMAP-1), x1c = min(max(x0+1, 0), FMAP-1);
    float v00 = g_minval[y0c*FMAP + x0c], v01 = g_minval[y0c*FMAP + x1c];
    float v10 = g_minval[y1c*FMAP + x0c], v11 = g_minval[y1c*FMAP + x1c];
    g_up[o] = (1.f-fy)*((1.f-fx)*v00 + fx*v01) + fy*((1.f-fx)*v10 + fx*v11);
}

__device__ __forceinline__ int refl(int q) {
    if (q < 0) q = -q;
    if (q > IMG-1) q = 2*(IMG-1) - q;
    return q;
}

__global__ void k_blurY() {
    int o = blockIdx.x*blockDim.x + threadIdx.x;
    if (o >= IMG*IMG) return;
    int oy = o / IMG, ox = o % IMG;
    float s = 0.f;
#pragma unroll
    for (int t = 0; t < KS; t++)
        s += g_gw[t] * g_up[refl(oy + t - KHALF)*IMG + ox];
    g_tmp[o] = s;
}

__global__ void k_blurX(float* __restrict__ map_out) {
    int o = blockIdx.x*blockDim.x + threadIdx.x;
    if (o >= IMG*IMG) return;
    int oy = o / IMG, ox = o % IMG;
    float s = 0.f;
#pragma unroll
    for (int t = 0; t < KS; t++)
        s += g_gw[t] * g_tmp[oy*IMG + refl(ox + t - KHALF)];
    map_out[o] = s;
}

/* ---------------- launch ---------------- */
extern "C" void kernel_launch(void* const* d_in, const int* in_sizes, int n_in,
                              void* d_out, int out_size) {
    const float* patch = (const float*)d_in[0];
    const float* lib   = (const float*)d_in[1];
    float* out = (float*)d_out;
    int has_scalar = (out_size > IMG*IMG) ? 1 : 0;
    float* map_out = out + has_scalar;

    cudaFuncSetAttribute(k_gemm, cudaFuncAttributeMaxDynamicSharedMemorySize, SMEM_SZ);

    k_prep<<<88, 256>>>(patch);                 /* patch fp16 conv + x2 + minpack */
    k_conv_lib<<<(M_LIB + 7)/8, 256>>>(lib);    /* lib fp16 conv + y2 */
    k_gemm<<<NBLK_M, 256, SMEM_SZ>>>();
    k_argmax<<<1, 1024>>>();
    k_wdist<<<WD_BLOCKS, 256>>>(lib);
    k_merge<<<1, 256>>>();
    k_score<<<1, 64>>>(patch, lib, out, has_scalar);
    k_weights<<<1, 1>>>();
    k_resize<<<196, 256>>>();
    k_blurY<<<196, 256>>>();
    k_blurX<<<196, 256>>>(map_out);
}